// round 4
// baseline (speedup 1.0000x reference)
#include <cuda_runtime.h>
#include <cstdint>

// ---------------------------------------------------------------------------
// MistralQuantizedMLP via int8 digit GEMMs (sm_80-class path: cp.async +
// ldmatrix + mma.sync.m16n8k32.s8 — tcgen05/TMA are 'a'-feature and this
// bench's PTX targets plain compute_103).
//
// Weights int8-valued -> exact s8. Activations -> 2 int8 digits w/ per-row
// scale: x ~= rs[m]*(d0 + d1/256). Accumulate each digit in exact int32 over
// full K, combine in fp32 epilogue: out = cs[n]*rs[m]*(S0 + S1/256).
// ---------------------------------------------------------------------------

static constexpr int MDIM = 4096, HDIM = 4096, IDIM = 14336;
static constexpr int BM = 128, BN = 128, BK = 64;
static constexpr int STAGES = 4, THREADS = 256;
static constexpr int ROWB = 80;                 // padded row pitch (bytes)
static constexpr int MAT_B = BM * ROWB;         // 10240
static constexpr int STAGE_B = 3 * MAT_B;       // 30720
static constexpr int SMEM_B = STAGES * STAGE_B; // 122880

// ---- static device scratch (allocation-free rule) ----
__device__ __align__(1024) int8_t g_w8g[(size_t)IDIM * HDIM];
__device__ __align__(1024) int8_t g_w8u[(size_t)IDIM * HDIM];
__device__ __align__(1024) int8_t g_w8d[(size_t)HDIM * IDIM];
__device__ __align__(1024) int8_t g_xd0[(size_t)MDIM * HDIM];
__device__ __align__(1024) int8_t g_xd1[(size_t)MDIM * HDIM];
__device__ __align__(1024) int8_t g_hd0[(size_t)MDIM * IDIM];
__device__ __align__(1024) int8_t g_hd1[(size_t)MDIM * IDIM];
__device__ __align__(1024) float  g_gate[(size_t)MDIM * IDIM];
__device__ __align__(1024) float  g_up[(size_t)MDIM * IDIM];
__device__ float g_rsx[MDIM];
__device__ float g_rsh[MDIM];

// ---------------------------------------------------------------------------
// PTX helpers
// ---------------------------------------------------------------------------
__device__ __forceinline__ void cp_async16(void* sdst, const void* gsrc) {
    uint32_t s = (uint32_t)__cvta_generic_to_shared(sdst);
    asm volatile("cp.async.cg.shared.global [%0], [%1], 16;" :: "r"(s), "l"(gsrc));
}
__device__ __forceinline__ void ldm_x4(uint32_t* a, uint32_t addr) {
    asm volatile("ldmatrix.sync.aligned.m8n8.x4.shared.b16 {%0,%1,%2,%3}, [%4];"
                 : "=r"(a[0]), "=r"(a[1]), "=r"(a[2]), "=r"(a[3]) : "r"(addr));
}
__device__ __forceinline__ void ldm_x2(uint32_t* b, uint32_t addr) {
    asm volatile("ldmatrix.sync.aligned.m8n8.x2.shared.b16 {%0,%1}, [%2];"
                 : "=r"(b[0]), "=r"(b[1]) : "r"(addr));
}
__device__ __forceinline__ void imma(int* c, const uint32_t* a, const uint32_t* b) {
    asm volatile(
        "mma.sync.aligned.m16n8k32.row.col.s32.s8.s8.s32 "
        "{%0,%1,%2,%3}, {%4,%5,%6,%7}, {%8,%9}, {%0,%1,%2,%3};"
        : "+r"(c[0]), "+r"(c[1]), "+r"(c[2]), "+r"(c[3])
        : "r"(a[0]), "r"(a[1]), "r"(a[2]), "r"(a[3]), "r"(b[0]), "r"(b[1]));
}

// ---------------------------------------------------------------------------
// int8 digit GEMM:  C[m,n] = cs[n]*rs[m]*( sum d0*w + sum d1*w / 256 )
// A0,A1 [M,K] int8 row-major; Bw [N,K] int8 row-major (K-contig both).
// ---------------------------------------------------------------------------
__global__ __launch_bounds__(THREADS, 1)
void k_gemm_i8(const int8_t* __restrict__ A0, const int8_t* __restrict__ A1,
               const int8_t* __restrict__ Bw,
               const float* __restrict__ cs, const float* __restrict__ rs,
               float* __restrict__ C, int N, int K) {
    extern __shared__ __align__(128) int8_t sm[];
    const int tid = threadIdx.x, lane = tid & 31, wid = tid >> 5;
    const int wm = wid >> 2, wn = wid & 3;     // 2 x 4 warp grid, tile 64x32
    const size_t bm = (size_t)blockIdx.x * BM;
    const size_t bn = (size_t)blockIdx.y * BN;

    const int8_t* gA0 = A0 + bm * K;
    const int8_t* gA1 = A1 + bm * K;
    const int8_t* gB  = Bw + bn * K;

    int acc0[4][4][4], acc1[4][4][4];
    #pragma unroll
    for (int i = 0; i < 4; i++)
        #pragma unroll
        for (int j = 0; j < 4; j++)
            #pragma unroll
            for (int r = 0; r < 4; r++) { acc0[i][j][r] = 0; acc1[i][j][r] = 0; }

    auto load_stage = [&](int s, int k0) {
        #pragma unroll
        for (int c = tid; c < 1536; c += THREADS) {      // 3 mats * 128 rows * 4 chunks
            int mat = c >> 9, rr = (c >> 2) & 127, ch = c & 3;
            const int8_t* src =
                (mat == 0 ? gA0 : (mat == 1 ? gA1 : gB)) + (size_t)rr * K + k0 + ch * 16;
            cp_async16(sm + s * STAGE_B + mat * MAT_B + rr * ROWB + ch * 16, src);
        }
        asm volatile("cp.async.commit_group;" ::: "memory");
    };

    const int KT = K / BK;
    load_stage(0, 0);
    load_stage(1, BK);
    load_stage(2, 2 * BK);

    // precomputed intra-warp ldmatrix offsets
    const int l16 = lane & 15;
    const uint32_t a_off = (uint32_t)((lane & 15) * ROWB + (lane >> 4) * 16);
    const uint32_t b_off = (uint32_t)((l16 & 7) * ROWB + ((l16 >> 3) & 1) * 16);
    const uint32_t smb = (uint32_t)__cvta_generic_to_shared(sm);

    for (int kt = 0; kt < KT; kt++) {
        asm volatile("cp.async.wait_group 2;" ::: "memory");
        __syncthreads();
        if (kt + 3 < KT) load_stage((kt + 3) & 3, (kt + 3) * BK);
        else asm volatile("cp.async.commit_group;" ::: "memory");

        const uint32_t st = smb + (uint32_t)((kt & 3) * STAGE_B);
        const uint32_t sA0 = st + (uint32_t)((wm * 64) * ROWB);
        const uint32_t sA1 = sA0 + (uint32_t)MAT_B;
        const uint32_t sB  = st + 2u * MAT_B + (uint32_t)((wn * 32) * ROWB);

        #pragma unroll
        for (int ks = 0; ks < 2; ks++) {
            const uint32_t kb = (uint32_t)(ks * 32);
            uint32_t bf[4][2];
            #pragma unroll
            for (int ni = 0; ni < 4; ni++)
                ldm_x2(bf[ni], sB + (uint32_t)(ni * 8 * ROWB) + b_off + kb);

            uint32_t af[4][4];
            #pragma unroll
            for (int mi = 0; mi < 4; mi++)
                ldm_x4(af[mi], sA0 + (uint32_t)(mi * 16 * ROWB) + a_off + kb);
            #pragma unroll
            for (int mi = 0; mi < 4; mi++)
                #pragma unroll
                for (int ni = 0; ni < 4; ni++)
                    imma(acc0[mi][ni], af[mi], bf[ni]);

            #pragma unroll
            for (int mi = 0; mi < 4; mi++)
                ldm_x4(af[mi], sA1 + (uint32_t)(mi * 16 * ROWB) + a_off + kb);
            #pragma unroll
            for (int mi = 0; mi < 4; mi++)
                #pragma unroll
                for (int ni = 0; ni < 4; ni++)
                    imma(acc1[mi][ni], af[mi], bf[ni]);
        }
    }

    // epilogue
    const int r0b = (int)bm + wm * 64;
    const int c0b = (int)bn + wn * 32;
    #pragma unroll
    for (int mi = 0; mi < 4; mi++) {
        const int r0 = r0b + mi * 16 + (lane >> 2);
        const float rs0 = __ldg(rs + r0);
        const float rs1 = __ldg(rs + r0 + 8);
        #pragma unroll
        for (int ni = 0; ni < 4; ni++) {
            const int c0 = c0b + ni * 8 + (lane & 3) * 2;
            const float s0 = __ldg(cs + c0), s1 = __ldg(cs + c0 + 1);
            float2 v0, v1;
            v0.x = ((float)acc0[mi][ni][0] + (float)acc1[mi][ni][0] * (1.f/256.f)) * s0 * rs0;
            v0.y = ((float)acc0[mi][ni][1] + (float)acc1[mi][ni][1] * (1.f/256.f)) * s1 * rs0;
            v1.x = ((float)acc0[mi][ni][2] + (float)acc1[mi][ni][2] * (1.f/256.f)) * s0 * rs1;
            v1.y = ((float)acc0[mi][ni][3] + (float)acc1[mi][ni][3] * (1.f/256.f)) * s1 * rs1;
            *reinterpret_cast<float2*>(C + (size_t)r0 * N + c0) = v0;
            *reinterpret_cast<float2*>(C + (size_t)(r0 + 8) * N + c0) = v1;
        }
    }
}

// ---------------------------------------------------------------------------
// Elementwise kernels
// ---------------------------------------------------------------------------
__global__ void k_w8(const int4* __restrict__ wq, char4* __restrict__ out, int n4) {
    int i = blockIdx.x * blockDim.x + threadIdx.x;
    int stride = gridDim.x * blockDim.x;
    for (; i < n4; i += stride) {
        int4 v = wq[i];
        out[i] = make_char4((char)v.x, (char)v.y, (char)v.z, (char)v.w);
    }
}

__device__ __forceinline__ float blk_max(float v, float* red, int tid, int nthr) {
    #pragma unroll
    for (int o = 16; o > 0; o >>= 1)
        v = fmaxf(v, __shfl_xor_sync(0xFFFFFFFFu, v, o));
    if ((tid & 31) == 0) red[tid >> 5] = v;
    __syncthreads();
    const int nw = nthr >> 5;
    if (tid < 32) {
        float m = (tid < nw) ? red[tid] : 0.0f;
        #pragma unroll
        for (int o = 16; o > 0; o >>= 1)
            m = fmaxf(m, __shfl_xor_sync(0xFFFFFFFFu, m, o));
        if (tid == 0) red[0] = m;
    }
    __syncthreads();
    return red[0];
}

__device__ __forceinline__ int pack8(const int* d, int o) {
    return (d[o] & 255) | ((d[o+1] & 255) << 8) | ((d[o+2] & 255) << 16) | ((d[o+3] & 255) << 24);
}

// one block per row of x: 256 thr x 16 floats = 4096
__global__ __launch_bounds__(256) void k_qx(const float4* __restrict__ x,
                                            int4* __restrict__ d0, int4* __restrict__ d1,
                                            float* __restrict__ rsc) {
    __shared__ float red[8];
    const int row = blockIdx.x, t = threadIdx.x;
    const float4* xr = x + (size_t)row * (HDIM / 4) + t * 4;
    float v[16];
    #pragma unroll
    for (int i = 0; i < 4; i++) {
        float4 f = xr[i];
        v[4*i] = f.x; v[4*i+1] = f.y; v[4*i+2] = f.z; v[4*i+3] = f.w;
    }
    float mx = 0.f;
    #pragma unroll
    for (int i = 0; i < 16; i++) mx = fmaxf(mx, fabsf(v[i]));
    mx = blk_max(mx, red, t, 256);
    const float s0 = fmaxf(mx, 1e-20f) * (1.0f / 127.0f);
    const float i0 = 1.0f / s0, i1 = 256.0f / s0;
    int q0[16], q1[16];
    #pragma unroll
    for (int i = 0; i < 16; i++) {
        int a = __float2int_rn(v[i] * i0);
        float r = fmaf((float)(-a), s0, v[i]);
        int b = max(-127, min(127, __float2int_rn(r * i1)));
        q0[i] = a; q1[i] = b;
    }
    const size_t o = (size_t)row * (HDIM / 16) + t;
    d0[o] = make_int4(pack8(q0,0), pack8(q0,4), pack8(q0,8), pack8(q0,12));
    d1[o] = make_int4(pack8(q1,0), pack8(q1,4), pack8(q1,8), pack8(q1,12));
    if (t == 0) rsc[row] = s0;
}

__device__ __forceinline__ float silu_f(float g) { return g / (1.0f + expf(-g)); }

// one block per row of h: 448 thr x 32 elems = 14336
__global__ __launch_bounds__(448) void k_qh(const float4* __restrict__ gate,
                                            const float4* __restrict__ up,
                                            int4* __restrict__ d0, int4* __restrict__ d1,
                                            float* __restrict__ rsc) {
    __shared__ float red[16];
    const int row = blockIdx.x, t = threadIdx.x;
    const float4* gr = gate + (size_t)row * (IDIM / 4) + t * 8;
    const float4* ur = up   + (size_t)row * (IDIM / 4) + t * 8;
    float h[32];
    #pragma unroll
    for (int i = 0; i < 8; i++) {
        float4 g = gr[i], u = ur[i];
        h[4*i]   = silu_f(g.x) * u.x;
        h[4*i+1] = silu_f(g.y) * u.y;
        h[4*i+2] = silu_f(g.z) * u.z;
        h[4*i+3] = silu_f(g.w) * u.w;
    }
    float mx = 0.f;
    #pragma unroll
    for (int i = 0; i < 32; i++) mx = fmaxf(mx, fabsf(h[i]));
    mx = blk_max(mx, red, t, 448);
    const float s0 = fmaxf(mx, 1e-20f) * (1.0f / 127.0f);
    const float i0 = 1.0f / s0, i1 = 256.0f / s0;
    int q0[32], q1[32];
    #pragma unroll
    for (int i = 0; i < 32; i++) {
        int a = __float2int_rn(h[i] * i0);
        float r = fmaf((float)(-a), s0, h[i]);
        int b = max(-127, min(127, __float2int_rn(r * i1)));
        q0[i] = a; q1[i] = b;
    }
    const size_t o = (size_t)row * (IDIM / 16) + t * 2;
    d0[o]   = make_int4(pack8(q0,0),  pack8(q0,4),  pack8(q0,8),  pack8(q0,12));
    d0[o+1] = make_int4(pack8(q0,16), pack8(q0,20), pack8(q0,24), pack8(q0,28));
    d1[o]   = make_int4(pack8(q1,0),  pack8(q1,4),  pack8(q1,8),  pack8(q1,12));
    d1[o+1] = make_int4(pack8(q1,16), pack8(q1,20), pack8(q1,24), pack8(q1,28));
    if (t == 0) rsc[row] = s0;
}

// ---------------------------------------------------------------------------
// Launch
// ---------------------------------------------------------------------------
extern "C" void kernel_launch(void* const* d_in, const int* in_sizes, int n_in,
                              void* d_out, int out_size) {
    const float* x   = (const float*)d_in[0];
    const int*   gwq = (const int*)  d_in[1];
    const float* gsc = (const float*)d_in[2];
    const int*   uwq = (const int*)  d_in[3];
    const float* usc = (const float*)d_in[4];
    const int*   dwq = (const int*)  d_in[5];
    const float* dsc = (const float*)d_in[6];
    float* out = (float*)d_out;

    cudaFuncSetAttribute(k_gemm_i8, cudaFuncAttributeMaxDynamicSharedMemorySize, SMEM_B);

    int8_t *w8g, *w8u, *w8d, *xd0, *xd1, *hd0, *hd1;
    float *gate, *up, *rsx, *rsh;
    cudaGetSymbolAddress((void**)&w8g, g_w8g);
    cudaGetSymbolAddress((void**)&w8u, g_w8u);
    cudaGetSymbolAddress((void**)&w8d, g_w8d);
    cudaGetSymbolAddress((void**)&xd0, g_xd0);
    cudaGetSymbolAddress((void**)&xd1, g_xd1);
    cudaGetSymbolAddress((void**)&hd0, g_hd0);
    cudaGetSymbolAddress((void**)&hd1, g_hd1);
    cudaGetSymbolAddress((void**)&gate, g_gate);
    cudaGetSymbolAddress((void**)&up,   g_up);
    cudaGetSymbolAddress((void**)&rsx,  g_rsx);
    cudaGetSymbolAddress((void**)&rsh,  g_rsh);

    {
        int n4 = IDIM * HDIM / 4;
        k_w8<<<2048, 256>>>((const int4*)gwq, (char4*)w8g, n4);
        k_w8<<<2048, 256>>>((const int4*)uwq, (char4*)w8u, n4);
        k_w8<<<2048, 256>>>((const int4*)dwq, (char4*)w8d, n4);
    }
    k_qx<<<MDIM, 256>>>((const float4*)x, (int4*)xd0, (int4*)xd1, rsx);

    dim3 grid1(MDIM / BM, IDIM / BN);   // (32, 112), x fastest for W-slab L2 reuse
    k_gemm_i8<<<grid1, THREADS, SMEM_B>>>(xd0, xd1, w8g, gsc, rsx, gate, IDIM, HDIM);
    k_gemm_i8<<<grid1, THREADS, SMEM_B>>>(xd0, xd1, w8u, usc, rsx, up,   IDIM, HDIM);

    k_qh<<<MDIM, 448>>>((const float4*)gate, (const float4*)up,
                        (int4*)hd0, (int4*)hd1, rsh);

    dim3 grid2(MDIM / BM, HDIM / BN);   // (32, 32)
    k_gemm_i8<<<grid2, THREADS, SMEM_B>>>(hd0, hd1, w8d, dsc, rsh, out, HDIM, IDIM);
}

// round 7
// speedup vs baseline: 2.7941x; 2.7941x over previous
#include <cuda_runtime.h>
#include <cuda_bf16.h>
#include <cstdint>

// ---------------------------------------------------------------------------
// MistralQuantizedMLP via bf16 hi/lo split GEMMs on legacy HMMA
// (mma.sync.m16n8k16.bf16) — the only fast tensor path reachable from the
// bench's plain compute_103 PTX target (tcgen05/TMA are 'a'-only; legacy
// IMMA measured quarter-rate in R4).
//
// Weights int8-valued -> exact in bf16, scale folded into epilogue.
// Activations split hi/lo bf16; both passes accumulate into one fp32 acc.
// R1 was smem-crossbar-bound (87% of 128B/cyc); this round: warp tile
// 64x64 (CTA 128x256) halves smem bytes/MAC; BK=64; 3-stage cp.async.
// ---------------------------------------------------------------------------

static constexpr int MDIM = 4096, HDIM = 4096, IDIM = 14336;
static constexpr int BM = 128, BN = 256, BK = 64;
static constexpr int THREADS = 256;
static constexpr int PITCH = 144;               // 128B row + 16B pad (conflict-free)
static constexpr int MAT_A = BM * PITCH;        // 18432
static constexpr int MAT_B = BN * PITCH;        // 36864
static constexpr int STAGE_B = 2 * MAT_A + MAT_B;   // 73728
static constexpr int STAGES = 3;
static constexpr int SMEM_B = STAGES * STAGE_B;     // 221184

// ---- static device scratch (allocation-free rule) ----
__device__ __align__(1024) __nv_bfloat16 g_wg[(size_t)IDIM * HDIM];
__device__ __align__(1024) __nv_bfloat16 g_wu[(size_t)IDIM * HDIM];
__device__ __align__(1024) __nv_bfloat16 g_wd[(size_t)HDIM * IDIM];
__device__ __align__(1024) __nv_bfloat16 g_xhi[(size_t)MDIM * HDIM];
__device__ __align__(1024) __nv_bfloat16 g_xlo[(size_t)MDIM * HDIM];
__device__ __align__(1024) float         g_gate[(size_t)MDIM * IDIM];
__device__ __align__(1024) float         g_up[(size_t)MDIM * IDIM];
__device__ __align__(1024) __nv_bfloat16 g_hhi[(size_t)MDIM * IDIM];
__device__ __align__(1024) __nv_bfloat16 g_hlo[(size_t)MDIM * IDIM];

// ---------------------------------------------------------------------------
// PTX helpers
// ---------------------------------------------------------------------------
__device__ __forceinline__ void cp_async16(void* sdst, const void* gsrc) {
    uint32_t s = (uint32_t)__cvta_generic_to_shared(sdst);
    asm volatile("cp.async.cg.shared.global [%0], [%1], 16;" :: "r"(s), "l"(gsrc));
}
__device__ __forceinline__ void ldm_x4(uint32_t* a, uint32_t addr) {
    asm volatile("ldmatrix.sync.aligned.m8n8.x4.shared.b16 {%0,%1,%2,%3}, [%4];"
                 : "=r"(a[0]), "=r"(a[1]), "=r"(a[2]), "=r"(a[3]) : "r"(addr));
}
__device__ __forceinline__ void mma16816(float* c, const uint32_t* a, const uint32_t* b) {
    asm volatile("mma.sync.aligned.m16n8k16.row.col.f32.bf16.bf16.f32 "
                 "{%0,%1,%2,%3}, {%4,%5,%6,%7}, {%8,%9}, {%0,%1,%2,%3};"
                 : "+f"(c[0]), "+f"(c[1]), "+f"(c[2]), "+f"(c[3])
                 : "r"(a[0]), "r"(a[1]), "r"(a[2]), "r"(a[3]), "r"(b[0]), "r"(b[1]));
}

// ---------------------------------------------------------------------------
// GEMM: C[m,n] = scale[n] * sum_k (Ahi+Alo)[m,k] * B[n,k]   (both K-contig)
// CTA 128x256, 8 warps (2m x 4n), warp tile 64x64, BK=64, 3-stage pipeline.
// ---------------------------------------------------------------------------
__global__ __launch_bounds__(THREADS, 1)
void k_gemm(const __nv_bfloat16* __restrict__ Ahi,
            const __nv_bfloat16* __restrict__ Alo,
            const __nv_bfloat16* __restrict__ Bw,
            const float* __restrict__ scale,
            float* __restrict__ C, int N, int K) {
    extern __shared__ __align__(128) int8_t sm[];
    const int tid = threadIdx.x, lane = tid & 31, wid = tid >> 5;
    const int wm = wid >> 2, wn = wid & 3;       // 2 x 4 -> warp tile 64x64
    const size_t bm = (size_t)blockIdx.x * BM;
    const size_t bn = (size_t)blockIdx.y * BN;

    const __nv_bfloat16* gA0 = Ahi + bm * K;
    const __nv_bfloat16* gA1 = Alo + bm * K;
    const __nv_bfloat16* gB  = Bw  + bn * K;

    float acc[4][8][4];
    #pragma unroll
    for (int i = 0; i < 4; i++)
        #pragma unroll
        for (int j = 0; j < 8; j++)
            #pragma unroll
            for (int r = 0; r < 4; r++) acc[i][j][r] = 0.0f;

    // stage chunk loads: 4096 x 16B per stage, 16 per thread
    auto load_stage = [&](int s, int k0) {
        int8_t* base = sm + s * STAGE_B;
        #pragma unroll
        for (int i = 0; i < 4; i++) {            // A_hi: 1024 chunks
            int c = tid + i * THREADS, row = c >> 3, ch = c & 7;
            cp_async16(base + row * PITCH + ch * 16,
                       gA0 + (size_t)row * K + k0 + ch * 8);
        }
        #pragma unroll
        for (int i = 0; i < 4; i++) {            // A_lo
            int c = tid + i * THREADS, row = c >> 3, ch = c & 7;
            cp_async16(base + MAT_A + row * PITCH + ch * 16,
                       gA1 + (size_t)row * K + k0 + ch * 8);
        }
        #pragma unroll
        for (int i = 0; i < 8; i++) {            // B: 2048 chunks
            int c = tid + i * THREADS, row = c >> 3, ch = c & 7;
            cp_async16(base + 2 * MAT_A + row * PITCH + ch * 16,
                       gB + (size_t)row * K + k0 + ch * 8);
        }
        asm volatile("cp.async.commit_group;" ::: "memory");
    };

    const int KT = K / BK;
    load_stage(0, 0);
    load_stage(1, BK);

    const uint32_t smb = (uint32_t)__cvta_generic_to_shared(sm);
    // A ldm_x4 (16x16): lanes 0-15 rows, 16-31 rows at +16B col
    const uint32_t a_off = (uint32_t)((lane & 15) * PITCH + (lane >> 4) * 16);
    // B ldm_x4 (two 8-row n-subtiles x two 16B k-halves):
    //   g = lane>>3: n_sub = g>>1, k_half = g&1
    const uint32_t b_off = (uint32_t)((lane & 7) * PITCH +
                                      ((lane >> 3) & 1) * 16 +
                                      (lane >> 4) * 8 * PITCH);

    int stage = 0;
    for (int kt = 0; kt < KT; kt++) {
        asm volatile("cp.async.wait_group 1;" ::: "memory");
        __syncthreads();
        if (kt + 2 < KT) {
            int s2 = stage + 2; if (s2 >= STAGES) s2 -= STAGES;
            load_stage(s2, (kt + 2) * BK);
        } else {
            asm volatile("cp.async.commit_group;" ::: "memory");
        }

        const uint32_t st  = smb + (uint32_t)(stage * STAGE_B);
        const uint32_t sA0 = st + (uint32_t)((wm * 64) * PITCH);
        const uint32_t sA1 = sA0 + (uint32_t)MAT_A;
        const uint32_t sB  = st + 2u * MAT_A + (uint32_t)((wn * 64) * PITCH);

        #pragma unroll
        for (int ks = 0; ks < 4; ks++) {
            const uint32_t kb = (uint32_t)(ks * 32);   // 16 elems = 32B
            uint32_t bf[8][2];
            #pragma unroll
            for (int np = 0; np < 4; np++) {
                uint32_t t4[4];
                ldm_x4(t4, sB + (uint32_t)(np * 16 * PITCH) + b_off + kb);
                bf[2 * np][0] = t4[0]; bf[2 * np][1] = t4[1];
                bf[2 * np + 1][0] = t4[2]; bf[2 * np + 1][1] = t4[3];
            }
            uint32_t af[4][4];
            #pragma unroll
            for (int mi = 0; mi < 4; mi++)
                ldm_x4(af[mi], sA0 + (uint32_t)(mi * 16 * PITCH) + a_off + kb);
            #pragma unroll
            for (int mi = 0; mi < 4; mi++)
                #pragma unroll
                for (int ni = 0; ni < 8; ni++)
                    mma16816(acc[mi][ni], af[mi], bf[ni]);
            #pragma unroll
            for (int mi = 0; mi < 4; mi++)
                ldm_x4(af[mi], sA1 + (uint32_t)(mi * 16 * PITCH) + a_off + kb);
            #pragma unroll
            for (int mi = 0; mi < 4; mi++)
                #pragma unroll
                for (int ni = 0; ni < 8; ni++)
                    mma16816(acc[mi][ni], af[mi], bf[ni]);
        }
        if (++stage == STAGES) stage = 0;
    }

    // epilogue: scale by per-output-channel factor, fp32 store
    const int r0b = (int)bm + wm * 64;
    const int c0b = (int)bn + wn * 64;
    #pragma unroll
    for (int mi = 0; mi < 4; mi++) {
        const int r0 = r0b + mi * 16 + (lane >> 2);
        #pragma unroll
        for (int ni = 0; ni < 8; ni++) {
            const int c0 = c0b + ni * 8 + (lane & 3) * 2;
            const float s0 = __ldg(scale + c0), s1 = __ldg(scale + c0 + 1);
            float2 v0 = make_float2(acc[mi][ni][0] * s0, acc[mi][ni][1] * s1);
            float2 v1 = make_float2(acc[mi][ni][2] * s0, acc[mi][ni][3] * s1);
            *reinterpret_cast<float2*>(C + (size_t)r0 * N + c0) = v0;
            *reinterpret_cast<float2*>(C + (size_t)(r0 + 8) * N + c0) = v1;
        }
    }
}

// ---------------------------------------------------------------------------
// Elementwise kernels (from R1, proven)
// ---------------------------------------------------------------------------
__global__ void k_convert_w(const int4* __restrict__ wq,
                            __nv_bfloat162* __restrict__ out, int n4) {
    int i = blockIdx.x * blockDim.x + threadIdx.x;
    int stride = gridDim.x * blockDim.x;
    for (; i < n4; i += stride) {
        int4 v = wq[i];
        out[2 * i + 0] = __halves2bfloat162(__float2bfloat16_rn((float)v.x),
                                            __float2bfloat16_rn((float)v.y));
        out[2 * i + 1] = __halves2bfloat162(__float2bfloat16_rn((float)v.z),
                                            __float2bfloat16_rn((float)v.w));
    }
}

__device__ __forceinline__ void split1(float v, __nv_bfloat16& h, __nv_bfloat16& l) {
    h = __float2bfloat16_rn(v);
    l = __float2bfloat16_rn(v - __bfloat162float(h));
}

__global__ void k_split_x(const float4* __restrict__ x,
                          __nv_bfloat162* __restrict__ hi,
                          __nv_bfloat162* __restrict__ lo, int n4) {
    int i = blockIdx.x * blockDim.x + threadIdx.x;
    int stride = gridDim.x * blockDim.x;
    for (; i < n4; i += stride) {
        float4 v = x[i];
        __nv_bfloat16 h0, l0, h1, l1, h2, l2, h3, l3;
        split1(v.x, h0, l0); split1(v.y, h1, l1);
        split1(v.z, h2, l2); split1(v.w, h3, l3);
        hi[2 * i + 0] = __halves2bfloat162(h0, h1);
        hi[2 * i + 1] = __halves2bfloat162(h2, h3);
        lo[2 * i + 0] = __halves2bfloat162(l0, l1);
        lo[2 * i + 1] = __halves2bfloat162(l2, l3);
    }
}

__device__ __forceinline__ float silu_f(float g) { return g / (1.0f + expf(-g)); }

__global__ void k_swiglu(const float4* __restrict__ gate,
                         const float4* __restrict__ up,
                         __nv_bfloat162* __restrict__ hhi,
                         __nv_bfloat162* __restrict__ hlo, int n4) {
    int i = blockIdx.x * blockDim.x + threadIdx.x;
    int stride = gridDim.x * blockDim.x;
    for (; i < n4; i += stride) {
        float4 g = gate[i];
        float4 u = up[i];
        float4 h;
        h.x = silu_f(g.x) * u.x;
        h.y = silu_f(g.y) * u.y;
        h.z = silu_f(g.z) * u.z;
        h.w = silu_f(g.w) * u.w;
        __nv_bfloat16 a0, b0, a1, b1, a2, b2, a3, b3;
        split1(h.x, a0, b0); split1(h.y, a1, b1);
        split1(h.z, a2, b2); split1(h.w, a3, b3);
        hhi[2 * i + 0] = __halves2bfloat162(a0, a1);
        hhi[2 * i + 1] = __halves2bfloat162(a2, a3);
        hlo[2 * i + 0] = __halves2bfloat162(b0, b1);
        hlo[2 * i + 1] = __halves2bfloat162(b2, b3);
    }
}

// ---------------------------------------------------------------------------
// Launch
// ---------------------------------------------------------------------------
extern "C" void kernel_launch(void* const* d_in, const int* in_sizes, int n_in,
                              void* d_out, int out_size) {
    const float* x   = (const float*)d_in[0];
    const int*   gwq = (const int*)  d_in[1];
    const float* gsc = (const float*)d_in[2];
    const int*   uwq = (const int*)  d_in[3];
    const float* usc = (const float*)d_in[4];
    const int*   dwq = (const int*)  d_in[5];
    const float* dsc = (const float*)d_in[6];
    float* out = (float*)d_out;

    cudaFuncSetAttribute(k_gemm, cudaFuncAttributeMaxDynamicSharedMemorySize, SMEM_B);

    __nv_bfloat16 *wg, *wu, *wd, *xhi, *xlo, *hhi, *hlo;
    float *gate, *up;
    cudaGetSymbolAddress((void**)&wg,  g_wg);
    cudaGetSymbolAddress((void**)&wu,  g_wu);
    cudaGetSymbolAddress((void**)&wd,  g_wd);
    cudaGetSymbolAddress((void**)&xhi, g_xhi);
    cudaGetSymbolAddress((void**)&xlo, g_xlo);
    cudaGetSymbolAddress((void**)&hhi, g_hhi);
    cudaGetSymbolAddress((void**)&hlo, g_hlo);
    cudaGetSymbolAddress((void**)&gate, g_gate);
    cudaGetSymbolAddress((void**)&up,   g_up);

    const int CT = 256;
    {
        int n4 = IDIM * HDIM / 4;
        k_convert_w<<<4096, CT>>>((const int4*)gwq, (__nv_bfloat162*)wg, n4);
        k_convert_w<<<4096, CT>>>((const int4*)uwq, (__nv_bfloat162*)wu, n4);
        k_convert_w<<<4096, CT>>>((const int4*)dwq, (__nv_bfloat162*)wd, n4);
    }
    k_split_x<<<4096, CT>>>((const float4*)x, (__nv_bfloat162*)xhi,
                            (__nv_bfloat162*)xlo, MDIM * HDIM / 4);

    dim3 grid1(MDIM / BM, IDIM / BN);   // (32, 56), x fastest for W-slab L2 reuse
    k_gemm<<<grid1, THREADS, SMEM_B>>>(xhi, xlo, wg, gsc, gate, IDIM, HDIM);
    k_gemm<<<grid1, THREADS, SMEM_B>>>(xhi, xlo, wu, usc, up,   IDIM, HDIM);

    k_swiglu<<<8192, CT>>>((const float4*)gate, (const float4*)up,
                           (__nv_bfloat162*)hhi, (__nv_bfloat162*)hlo,
                           MDIM * IDIM / 4);

    dim3 grid2(MDIM / BM, HDIM / BN);   // (32, 16)
    k_gemm<<<grid2, THREADS, SMEM_B>>>(hhi, hlo, wd, dsc, out, HDIM, IDIM);
}

// round 8
// speedup vs baseline: 2.7984x; 1.0016x over previous
#include <cuda_runtime.h>
#include <cuda_bf16.h>
#include <cstdint>

// ---------------------------------------------------------------------------
// MistralQuantizedMLP via bf16 hi/lo split GEMMs on legacy HMMA
// (mma.sync.m16n8k16.bf16) — only fast tensor path from compute_103 PTX.
//
// R8: fuse gate+up GEMMs into one kernel; SwiGLU + hi/lo split in epilogue
// (no fp32 gate/up roundtrip through DRAM). Down GEMM = proven R7 kernel.
// ---------------------------------------------------------------------------

static constexpr int MDIM = 4096, HDIM = 4096, IDIM = 14336;
static constexpr int THREADS = 256;
static constexpr int PITCH = 144;               // 128B row + 16B pad

// ---- down-GEMM (R7) geometry: CTA 128x256, warp 64x64 ----
static constexpr int BM = 128, BN = 256, BK = 64;
static constexpr int MAT_A = BM * PITCH;            // 18432
static constexpr int MAT_B = BN * PITCH;            // 36864
static constexpr int STAGE_B = 2 * MAT_A + MAT_B;   // 73728
static constexpr int STAGES = 3;
static constexpr int SMEM_B = STAGES * STAGE_B;     // 221184

// ---- fused gate/up geometry: CTA 128x(128 pair), warp 64x(32 pair) ----
static constexpr int MAT2 = 128 * PITCH;            // 18432
static constexpr int STAGE2 = 4 * MAT2;             // A0,A1,Bg,Bu = 73728
static constexpr int SMEM2 = STAGES * STAGE2;       // 221184

// ---- static device scratch (allocation-free rule) ----
__device__ __align__(1024) __nv_bfloat16 g_wg[(size_t)IDIM * HDIM];
__device__ __align__(1024) __nv_bfloat16 g_wu[(size_t)IDIM * HDIM];
__device__ __align__(1024) __nv_bfloat16 g_wd[(size_t)HDIM * IDIM];
__device__ __align__(1024) __nv_bfloat16 g_xhi[(size_t)MDIM * HDIM];
__device__ __align__(1024) __nv_bfloat16 g_xlo[(size_t)MDIM * HDIM];
__device__ __align__(1024) __nv_bfloat16 g_hhi[(size_t)MDIM * IDIM];
__device__ __align__(1024) __nv_bfloat16 g_hlo[(size_t)MDIM * IDIM];

// ---------------------------------------------------------------------------
// PTX helpers
// ---------------------------------------------------------------------------
__device__ __forceinline__ void cp_async16(void* sdst, const void* gsrc) {
    uint32_t s = (uint32_t)__cvta_generic_to_shared(sdst);
    asm volatile("cp.async.cg.shared.global [%0], [%1], 16;" :: "r"(s), "l"(gsrc));
}
__device__ __forceinline__ void ldm_x4(uint32_t* a, uint32_t addr) {
    asm volatile("ldmatrix.sync.aligned.m8n8.x4.shared.b16 {%0,%1,%2,%3}, [%4];"
                 : "=r"(a[0]), "=r"(a[1]), "=r"(a[2]), "=r"(a[3]) : "r"(addr));
}
__device__ __forceinline__ void mma16816(float* c, const uint32_t* a, const uint32_t* b) {
    asm volatile("mma.sync.aligned.m16n8k16.row.col.f32.bf16.bf16.f32 "
                 "{%0,%1,%2,%3}, {%4,%5,%6,%7}, {%8,%9}, {%0,%1,%2,%3};"
                 : "+f"(c[0]), "+f"(c[1]), "+f"(c[2]), "+f"(c[3])
                 : "r"(a[0]), "r"(a[1]), "r"(a[2]), "r"(a[3]), "r"(b[0]), "r"(b[1]));
}
__device__ __forceinline__ void split1(float v, __nv_bfloat16& h, __nv_bfloat16& l) {
    h = __float2bfloat16_rn(v);
    l = __float2bfloat16_rn(v - __bfloat162float(h));
}
__device__ __forceinline__ float silu_f(float g) { return g / (1.0f + expf(-g)); }

// ---------------------------------------------------------------------------
// Fused gate+up GEMM + SwiGLU + hi/lo split epilogue.
// CTA: M=128, N=128 (both matrices). Warp: 64 x 32 pair. 8 warps.
// ---------------------------------------------------------------------------
__global__ __launch_bounds__(THREADS, 1)
void k_gemm_gu(const __nv_bfloat16* __restrict__ Ahi,
               const __nv_bfloat16* __restrict__ Alo,
               const __nv_bfloat16* __restrict__ Bg,
               const __nv_bfloat16* __restrict__ Bu,
               const float* __restrict__ gs, const float* __restrict__ us,
               __nv_bfloat16* __restrict__ Hhi, __nv_bfloat16* __restrict__ Hlo,
               int K) {
    extern __shared__ __align__(128) int8_t sm[];
    const int tid = threadIdx.x, lane = tid & 31, wid = tid >> 5;
    const int wm = wid >> 2, wn = wid & 3;       // warp tile 64 x 32(pair)
    const size_t bm = (size_t)blockIdx.x * 128;
    const size_t bn = (size_t)blockIdx.y * 128;

    const __nv_bfloat16* gA0 = Ahi + bm * K;
    const __nv_bfloat16* gA1 = Alo + bm * K;
    const __nv_bfloat16* gBg = Bg + bn * K;
    const __nv_bfloat16* gBu = Bu + bn * K;

    float accg[4][4][4], accu[4][4][4];
    #pragma unroll
    for (int i = 0; i < 4; i++)
        #pragma unroll
        for (int j = 0; j < 4; j++)
            #pragma unroll
            for (int r = 0; r < 4; r++) { accg[i][j][r] = 0.f; accu[i][j][r] = 0.f; }

    auto load_stage = [&](int s, int k0) {
        int8_t* base = sm + s * STAGE2;
        #pragma unroll
        for (int i = 0; i < 4; i++) {
            int c = tid + i * THREADS, row = c >> 3, ch = c & 7;
            cp_async16(base + row * PITCH + ch * 16, gA0 + (size_t)row * K + k0 + ch * 8);
        }
        #pragma unroll
        for (int i = 0; i < 4; i++) {
            int c = tid + i * THREADS, row = c >> 3, ch = c & 7;
            cp_async16(base + MAT2 + row * PITCH + ch * 16,
                       gA1 + (size_t)row * K + k0 + ch * 8);
        }
        #pragma unroll
        for (int i = 0; i < 4; i++) {
            int c = tid + i * THREADS, row = c >> 3, ch = c & 7;
            cp_async16(base + 2 * MAT2 + row * PITCH + ch * 16,
                       gBg + (size_t)row * K + k0 + ch * 8);
        }
        #pragma unroll
        for (int i = 0; i < 4; i++) {
            int c = tid + i * THREADS, row = c >> 3, ch = c & 7;
            cp_async16(base + 3 * MAT2 + row * PITCH + ch * 16,
                       gBu + (size_t)row * K + k0 + ch * 8);
        }
        asm volatile("cp.async.commit_group;" ::: "memory");
    };

    const int KT = K / BK;
    load_stage(0, 0);
    load_stage(1, BK);

    const uint32_t smb = (uint32_t)__cvta_generic_to_shared(sm);
    const uint32_t a_off = (uint32_t)((lane & 15) * PITCH + (lane >> 4) * 16);
    const uint32_t b_off = (uint32_t)((lane & 7) * PITCH +
                                      ((lane >> 3) & 1) * 16 +
                                      (lane >> 4) * 8 * PITCH);

    int stage = 0;
    for (int kt = 0; kt < KT; kt++) {
        asm volatile("cp.async.wait_group 1;" ::: "memory");
        __syncthreads();
        if (kt + 2 < KT) {
            int s2 = stage + 2; if (s2 >= STAGES) s2 -= STAGES;
            load_stage(s2, (kt + 2) * BK);
        } else {
            asm volatile("cp.async.commit_group;" ::: "memory");
        }

        const uint32_t st  = smb + (uint32_t)(stage * STAGE2);
        const uint32_t sA0 = st + (uint32_t)((wm * 64) * PITCH);
        const uint32_t sA1 = sA0 + (uint32_t)MAT2;
        const uint32_t sBg = st + 2u * MAT2 + (uint32_t)((wn * 32) * PITCH);
        const uint32_t sBu = st + 3u * MAT2 + (uint32_t)((wn * 32) * PITCH);

        #pragma unroll
        for (int ks = 0; ks < 4; ks++) {
            const uint32_t kb = (uint32_t)(ks * 32);
            uint32_t bg[4][2], bu[4][2];
            #pragma unroll
            for (int np = 0; np < 2; np++) {
                uint32_t t4[4];
                ldm_x4(t4, sBg + (uint32_t)(np * 16 * PITCH) + b_off + kb);
                bg[2*np][0] = t4[0]; bg[2*np][1] = t4[1];
                bg[2*np+1][0] = t4[2]; bg[2*np+1][1] = t4[3];
                ldm_x4(t4, sBu + (uint32_t)(np * 16 * PITCH) + b_off + kb);
                bu[2*np][0] = t4[0]; bu[2*np][1] = t4[1];
                bu[2*np+1][0] = t4[2]; bu[2*np+1][1] = t4[3];
            }
            uint32_t af[4][4];
            #pragma unroll
            for (int mi = 0; mi < 4; mi++)
                ldm_x4(af[mi], sA0 + (uint32_t)(mi * 16 * PITCH) + a_off + kb);
            #pragma unroll
            for (int mi = 0; mi < 4; mi++)
                #pragma unroll
                for (int ni = 0; ni < 4; ni++) {
                    mma16816(accg[mi][ni], af[mi], bg[ni]);
                    mma16816(accu[mi][ni], af[mi], bu[ni]);
                }
            #pragma unroll
            for (int mi = 0; mi < 4; mi++)
                ldm_x4(af[mi], sA1 + (uint32_t)(mi * 16 * PITCH) + a_off + kb);
            #pragma unroll
            for (int mi = 0; mi < 4; mi++)
                #pragma unroll
                for (int ni = 0; ni < 4; ni++) {
                    mma16816(accg[mi][ni], af[mi], bg[ni]);
                    mma16816(accu[mi][ni], af[mi], bu[ni]);
                }
        }
        if (++stage == STAGES) stage = 0;
    }

    // epilogue: scales -> SwiGLU -> hi/lo bf16 split -> store
    const int r0b = (int)bm + wm * 64;
    const int c0b = (int)bn + wn * 32;
    #pragma unroll
    for (int mi = 0; mi < 4; mi++) {
        const int r0 = r0b + mi * 16 + (lane >> 2);
        #pragma unroll
        for (int ni = 0; ni < 4; ni++) {
            const int c0 = c0b + ni * 8 + (lane & 3) * 2;
            const float gs0 = __ldg(gs + c0), gs1 = __ldg(gs + c0 + 1);
            const float us0 = __ldg(us + c0), us1 = __ldg(us + c0 + 1);
            float h00 = silu_f(accg[mi][ni][0] * gs0) * (accu[mi][ni][0] * us0);
            float h01 = silu_f(accg[mi][ni][1] * gs1) * (accu[mi][ni][1] * us1);
            float h10 = silu_f(accg[mi][ni][2] * gs0) * (accu[mi][ni][2] * us0);
            float h11 = silu_f(accg[mi][ni][3] * gs1) * (accu[mi][ni][3] * us1);
            __nv_bfloat16 a0, b0, a1, b1, a2, b2, a3, b3;
            split1(h00, a0, b0); split1(h01, a1, b1);
            split1(h10, a2, b2); split1(h11, a3, b3);
            *reinterpret_cast<__nv_bfloat162*>(Hhi + (size_t)r0 * IDIM + c0) =
                __halves2bfloat162(a0, a1);
            *reinterpret_cast<__nv_bfloat162*>(Hlo + (size_t)r0 * IDIM + c0) =
                __halves2bfloat162(b0, b1);
            *reinterpret_cast<__nv_bfloat162*>(Hhi + (size_t)(r0 + 8) * IDIM + c0) =
                __halves2bfloat162(a2, a3);
            *reinterpret_cast<__nv_bfloat162*>(Hlo + (size_t)(r0 + 8) * IDIM + c0) =
                __halves2bfloat162(b2, b3);
        }
    }
}

// ---------------------------------------------------------------------------
// Down GEMM (R7, proven): C[m,n] = scale[n]*sum_k (Ahi+Alo)[m,k]*B[n,k]
// ---------------------------------------------------------------------------
__global__ __launch_bounds__(THREADS, 1)
void k_gemm(const __nv_bfloat16* __restrict__ Ahi,
            const __nv_bfloat16* __restrict__ Alo,
            const __nv_bfloat16* __restrict__ Bw,
            const float* __restrict__ scale,
            float* __restrict__ C, int N, int K) {
    extern __shared__ __align__(128) int8_t sm[];
    const int tid = threadIdx.x, lane = tid & 31, wid = tid >> 5;
    const int wm = wid >> 2, wn = wid & 3;
    const size_t bm = (size_t)blockIdx.x * BM;
    const size_t bn = (size_t)blockIdx.y * BN;

    const __nv_bfloat16* gA0 = Ahi + bm * K;
    const __nv_bfloat16* gA1 = Alo + bm * K;
    const __nv_bfloat16* gB  = Bw  + bn * K;

    float acc[4][8][4];
    #pragma unroll
    for (int i = 0; i < 4; i++)
        #pragma unroll
        for (int j = 0; j < 8; j++)
            #pragma unroll
            for (int r = 0; r < 4; r++) acc[i][j][r] = 0.0f;

    auto load_stage = [&](int s, int k0) {
        int8_t* base = sm + s * STAGE_B;
        #pragma unroll
        for (int i = 0; i < 4; i++) {
            int c = tid + i * THREADS, row = c >> 3, ch = c & 7;
            cp_async16(base + row * PITCH + ch * 16, gA0 + (size_t)row * K + k0 + ch * 8);
        }
        #pragma unroll
        for (int i = 0; i < 4; i++) {
            int c = tid + i * THREADS, row = c >> 3, ch = c & 7;
            cp_async16(base + MAT_A + row * PITCH + ch * 16,
                       gA1 + (size_t)row * K + k0 + ch * 8);
        }
        #pragma unroll
        for (int i = 0; i < 8; i++) {
            int c = tid + i * THREADS, row = c >> 3, ch = c & 7;
            cp_async16(base + 2 * MAT_A + row * PITCH + ch * 16,
                       gB + (size_t)row * K + k0 + ch * 8);
        }
        asm volatile("cp.async.commit_group;" ::: "memory");
    };

    const int KT = K / BK;
    load_stage(0, 0);
    load_stage(1, BK);

    const uint32_t smb = (uint32_t)__cvta_generic_to_shared(sm);
    const uint32_t a_off = (uint32_t)((lane & 15) * PITCH + (lane >> 4) * 16);
    const uint32_t b_off = (uint32_t)((lane & 7) * PITCH +
                                      ((lane >> 3) & 1) * 16 +
                                      (lane >> 4) * 8 * PITCH);

    int stage = 0;
    for (int kt = 0; kt < KT; kt++) {
        asm volatile("cp.async.wait_group 1;" ::: "memory");
        __syncthreads();
        if (kt + 2 < KT) {
            int s2 = stage + 2; if (s2 >= STAGES) s2 -= STAGES;
            load_stage(s2, (kt + 2) * BK);
        } else {
            asm volatile("cp.async.commit_group;" ::: "memory");
        }

        const uint32_t st  = smb + (uint32_t)(stage * STAGE_B);
        const uint32_t sA0 = st + (uint32_t)((wm * 64) * PITCH);
        const uint32_t sA1 = sA0 + (uint32_t)MAT_A;
        const uint32_t sB  = st + 2u * MAT_A + (uint32_t)((wn * 64) * PITCH);

        #pragma unroll
        for (int ks = 0; ks < 4; ks++) {
            const uint32_t kb = (uint32_t)(ks * 32);
            uint32_t bf[8][2];
            #pragma unroll
            for (int np = 0; np < 4; np++) {
                uint32_t t4[4];
                ldm_x4(t4, sB + (uint32_t)(np * 16 * PITCH) + b_off + kb);
                bf[2 * np][0] = t4[0]; bf[2 * np][1] = t4[1];
                bf[2 * np + 1][0] = t4[2]; bf[2 * np + 1][1] = t4[3];
            }
            uint32_t af[4][4];
            #pragma unroll
            for (int mi = 0; mi < 4; mi++)
                ldm_x4(af[mi], sA0 + (uint32_t)(mi * 16 * PITCH) + a_off + kb);
            #pragma unroll
            for (int mi = 0; mi < 4; mi++)
                #pragma unroll
                for (int ni = 0; ni < 8; ni++)
                    mma16816(acc[mi][ni], af[mi], bf[ni]);
            #pragma unroll
            for (int mi = 0; mi < 4; mi++)
                ldm_x4(af[mi], sA1 + (uint32_t)(mi * 16 * PITCH) + a_off + kb);
            #pragma unroll
            for (int mi = 0; mi < 4; mi++)
                #pragma unroll
                for (int ni = 0; ni < 8; ni++)
                    mma16816(acc[mi][ni], af[mi], bf[ni]);
        }
        if (++stage == STAGES) stage = 0;
    }

    const int r0b = (int)bm + wm * 64;
    const int c0b = (int)bn + wn * 64;
    #pragma unroll
    for (int mi = 0; mi < 4; mi++) {
        const int r0 = r0b + mi * 16 + (lane >> 2);
        #pragma unroll
        for (int ni = 0; ni < 8; ni++) {
            const int c0 = c0b + ni * 8 + (lane & 3) * 2;
            const float s0 = __ldg(scale + c0), s1 = __ldg(scale + c0 + 1);
            float2 v0 = make_float2(acc[mi][ni][0] * s0, acc[mi][ni][1] * s1);
            float2 v1 = make_float2(acc[mi][ni][2] * s0, acc[mi][ni][3] * s1);
            *reinterpret_cast<float2*>(C + (size_t)r0 * N + c0) = v0;
            *reinterpret_cast<float2*>(C + (size_t)(r0 + 8) * N + c0) = v1;
        }
    }
}

// ---------------------------------------------------------------------------
// Elementwise prep kernels
// ---------------------------------------------------------------------------
__global__ void k_convert_w(const int4* __restrict__ wq,
                            __nv_bfloat162* __restrict__ out, int n4) {
    int i = blockIdx.x * blockDim.x + threadIdx.x;
    int stride = gridDim.x * blockDim.x;
    for (; i < n4; i += stride) {
        int4 v = wq[i];
        out[2 * i + 0] = __halves2bfloat162(__float2bfloat16_rn((float)v.x),
                                            __float2bfloat16_rn((float)v.y));
        out[2 * i + 1] = __halves2bfloat162(__float2bfloat16_rn((float)v.z),
                                            __float2bfloat16_rn((float)v.w));
    }
}

__global__ void k_split_x(const float4* __restrict__ x,
                          __nv_bfloat162* __restrict__ hi,
                          __nv_bfloat162* __restrict__ lo, int n4) {
    int i = blockIdx.x * blockDim.x + threadIdx.x;
    int stride = gridDim.x * blockDim.x;
    for (; i < n4; i += stride) {
        float4 v = x[i];
        __nv_bfloat16 h0, l0, h1, l1, h2, l2, h3, l3;
        split1(v.x, h0, l0); split1(v.y, h1, l1);
        split1(v.z, h2, l2); split1(v.w, h3, l3);
        hi[2 * i + 0] = __halves2bfloat162(h0, h1);
        hi[2 * i + 1] = __halves2bfloat162(h2, h3);
        lo[2 * i + 0] = __halves2bfloat162(l0, l1);
        lo[2 * i + 1] = __halves2bfloat162(l2, l3);
    }
}

// ---------------------------------------------------------------------------
// Launch
// ---------------------------------------------------------------------------
extern "C" void kernel_launch(void* const* d_in, const int* in_sizes, int n_in,
                              void* d_out, int out_size) {
    const float* x   = (const float*)d_in[0];
    const int*   gwq = (const int*)  d_in[1];
    const float* gsc = (const float*)d_in[2];
    const int*   uwq = (const int*)  d_in[3];
    const float* usc = (const float*)d_in[4];
    const int*   dwq = (const int*)  d_in[5];
    const float* dsc = (const float*)d_in[6];
    float* out = (float*)d_out;

    cudaFuncSetAttribute(k_gemm,    cudaFuncAttributeMaxDynamicSharedMemorySize, SMEM_B);
    cudaFuncSetAttribute(k_gemm_gu, cudaFuncAttributeMaxDynamicSharedMemorySize, SMEM2);

    __nv_bfloat16 *wg, *wu, *wd, *xhi, *xlo, *hhi, *hlo;
    cudaGetSymbolAddress((void**)&wg,  g_wg);
    cudaGetSymbolAddress((void**)&wu,  g_wu);
    cudaGetSymbolAddress((void**)&wd,  g_wd);
    cudaGetSymbolAddress((void**)&xhi, g_xhi);
    cudaGetSymbolAddress((void**)&xlo, g_xlo);
    cudaGetSymbolAddress((void**)&hhi, g_hhi);
    cudaGetSymbolAddress((void**)&hlo, g_hlo);

    const int CT = 256;
    {
        int n4 = IDIM * HDIM / 4;
        k_convert_w<<<4096, CT>>>((const int4*)gwq, (__nv_bfloat162*)wg, n4);
        k_convert_w<<<4096, CT>>>((const int4*)uwq, (__nv_bfloat162*)wu, n4);
        k_convert_w<<<4096, CT>>>((const int4*)dwq, (__nv_bfloat162*)wd, n4);
    }
    k_split_x<<<4096, CT>>>((const float4*)x, (__nv_bfloat162*)xhi,
                            (__nv_bfloat162*)xlo, MDIM * HDIM / 4);

    dim3 grid1(MDIM / 128, IDIM / 128);   // (32, 112), m fastest for W-slab L2 reuse
    k_gemm_gu<<<grid1, THREADS, SMEM2>>>(xhi, xlo, wg, wu, gsc, usc, hhi, hlo, HDIM);

    dim3 grid2(MDIM / BM, HDIM / BN);     // (32, 16)
    k_gemm<<<grid2, THREADS, SMEM_B>>>(hhi, hlo, wd, dsc, out, HDIM, IDIM);
}

// round 9
// speedup vs baseline: 2.9111x; 1.0403x over previous
#include <cuda_runtime.h>
#include <cuda_bf16.h>
#include <cstdint>

// ---------------------------------------------------------------------------
// MistralQuantizedMLP via bf16 hi/lo split GEMMs on legacy HMMA
// (mma.sync.m16n8k16.bf16) — only fast tensor path from compute_103 PTX.
//
// R9: split-K=2 on the down GEMM (512 -> 1024 CTAs, wave util 86.5% -> 99%)
// with fp32 partial buffers + add kernel; ILP-2 weight conversion.
// Gate/up fused GEMM + SwiGLU/split epilogue unchanged from R8.
// ---------------------------------------------------------------------------

static constexpr int MDIM = 4096, HDIM = 4096, IDIM = 14336;
static constexpr int THREADS = 256;
static constexpr int PITCH = 144;               // 128B row + 16B pad

// ---- down-GEMM geometry: CTA 128x256, warp 64x64 ----
static constexpr int BM = 128, BN = 256, BK = 64;
static constexpr int MAT_A = BM * PITCH;            // 18432
static constexpr int MAT_B = BN * PITCH;            // 36864
static constexpr int STAGE_B = 2 * MAT_A + MAT_B;   // 73728
static constexpr int STAGES = 3;
static constexpr int SMEM_B = STAGES * STAGE_B;     // 221184

// ---- fused gate/up geometry: CTA 128x(128 pair), warp 64x(32 pair) ----
static constexpr int MAT2 = 128 * PITCH;            // 18432
static constexpr int STAGE2 = 4 * MAT2;             // A0,A1,Bg,Bu = 73728
static constexpr int SMEM2 = STAGES * STAGE2;       // 221184

// ---- static device scratch (allocation-free rule) ----
__device__ __align__(1024) __nv_bfloat16 g_wg[(size_t)IDIM * HDIM];
__device__ __align__(1024) __nv_bfloat16 g_wu[(size_t)IDIM * HDIM];
__device__ __align__(1024) __nv_bfloat16 g_wd[(size_t)HDIM * IDIM];
__device__ __align__(1024) __nv_bfloat16 g_xhi[(size_t)MDIM * HDIM];
__device__ __align__(1024) __nv_bfloat16 g_xlo[(size_t)MDIM * HDIM];
__device__ __align__(1024) __nv_bfloat16 g_hhi[(size_t)MDIM * IDIM];
__device__ __align__(1024) __nv_bfloat16 g_hlo[(size_t)MDIM * IDIM];
__device__ __align__(1024) float         g_part[2 * (size_t)MDIM * HDIM];

// ---------------------------------------------------------------------------
// PTX helpers
// ---------------------------------------------------------------------------
__device__ __forceinline__ void cp_async16(void* sdst, const void* gsrc) {
    uint32_t s = (uint32_t)__cvta_generic_to_shared(sdst);
    asm volatile("cp.async.cg.shared.global [%0], [%1], 16;" :: "r"(s), "l"(gsrc));
}
__device__ __forceinline__ void ldm_x4(uint32_t* a, uint32_t addr) {
    asm volatile("ldmatrix.sync.aligned.m8n8.x4.shared.b16 {%0,%1,%2,%3}, [%4];"
                 : "=r"(a[0]), "=r"(a[1]), "=r"(a[2]), "=r"(a[3]) : "r"(addr));
}
__device__ __forceinline__ void mma16816(float* c, const uint32_t* a, const uint32_t* b) {
    asm volatile("mma.sync.aligned.m16n8k16.row.col.f32.bf16.bf16.f32 "
                 "{%0,%1,%2,%3}, {%4,%5,%6,%7}, {%8,%9}, {%0,%1,%2,%3};"
                 : "+f"(c[0]), "+f"(c[1]), "+f"(c[2]), "+f"(c[3])
                 : "r"(a[0]), "r"(a[1]), "r"(a[2]), "r"(a[3]), "r"(b[0]), "r"(b[1]));
}
__device__ __forceinline__ void split1(float v, __nv_bfloat16& h, __nv_bfloat16& l) {
    h = __float2bfloat16_rn(v);
    l = __float2bfloat16_rn(v - __bfloat162float(h));
}
__device__ __forceinline__ float silu_f(float g) { return g / (1.0f + expf(-g)); }

// ---------------------------------------------------------------------------
// Fused gate+up GEMM + SwiGLU + hi/lo split epilogue (R8, proven).
// CTA: M=128, N=128 (both matrices). Warp: 64 x 32 pair. 8 warps.
// ---------------------------------------------------------------------------
__global__ __launch_bounds__(THREADS, 1)
void k_gemm_gu(const __nv_bfloat16* __restrict__ Ahi,
               const __nv_bfloat16* __restrict__ Alo,
               const __nv_bfloat16* __restrict__ Bg,
               const __nv_bfloat16* __restrict__ Bu,
               const float* __restrict__ gs, const float* __restrict__ us,
               __nv_bfloat16* __restrict__ Hhi, __nv_bfloat16* __restrict__ Hlo,
               int K) {
    extern __shared__ __align__(128) int8_t sm[];
    const int tid = threadIdx.x, lane = tid & 31, wid = tid >> 5;
    const int wm = wid >> 2, wn = wid & 3;
    const size_t bm = (size_t)blockIdx.x * 128;
    const size_t bn = (size_t)blockIdx.y * 128;

    const __nv_bfloat16* gA0 = Ahi + bm * K;
    const __nv_bfloat16* gA1 = Alo + bm * K;
    const __nv_bfloat16* gBg = Bg + bn * K;
    const __nv_bfloat16* gBu = Bu + bn * K;

    float accg[4][4][4], accu[4][4][4];
    #pragma unroll
    for (int i = 0; i < 4; i++)
        #pragma unroll
        for (int j = 0; j < 4; j++)
            #pragma unroll
            for (int r = 0; r < 4; r++) { accg[i][j][r] = 0.f; accu[i][j][r] = 0.f; }

    auto load_stage = [&](int s, int k0) {
        int8_t* base = sm + s * STAGE2;
        #pragma unroll
        for (int i = 0; i < 4; i++) {
            int c = tid + i * THREADS, row = c >> 3, ch = c & 7;
            cp_async16(base + row * PITCH + ch * 16, gA0 + (size_t)row * K + k0 + ch * 8);
        }
        #pragma unroll
        for (int i = 0; i < 4; i++) {
            int c = tid + i * THREADS, row = c >> 3, ch = c & 7;
            cp_async16(base + MAT2 + row * PITCH + ch * 16,
                       gA1 + (size_t)row * K + k0 + ch * 8);
        }
        #pragma unroll
        for (int i = 0; i < 4; i++) {
            int c = tid + i * THREADS, row = c >> 3, ch = c & 7;
            cp_async16(base + 2 * MAT2 + row * PITCH + ch * 16,
                       gBg + (size_t)row * K + k0 + ch * 8);
        }
        #pragma unroll
        for (int i = 0; i < 4; i++) {
            int c = tid + i * THREADS, row = c >> 3, ch = c & 7;
            cp_async16(base + 3 * MAT2 + row * PITCH + ch * 16,
                       gBu + (size_t)row * K + k0 + ch * 8);
        }
        asm volatile("cp.async.commit_group;" ::: "memory");
    };

    const int KT = K / BK;
    load_stage(0, 0);
    load_stage(1, BK);

    const uint32_t smb = (uint32_t)__cvta_generic_to_shared(sm);
    const uint32_t a_off = (uint32_t)((lane & 15) * PITCH + (lane >> 4) * 16);
    const uint32_t b_off = (uint32_t)((lane & 7) * PITCH +
                                      ((lane >> 3) & 1) * 16 +
                                      (lane >> 4) * 8 * PITCH);

    int stage = 0;
    for (int kt = 0; kt < KT; kt++) {
        asm volatile("cp.async.wait_group 1;" ::: "memory");
        __syncthreads();
        if (kt + 2 < KT) {
            int s2 = stage + 2; if (s2 >= STAGES) s2 -= STAGES;
            load_stage(s2, (kt + 2) * BK);
        } else {
            asm volatile("cp.async.commit_group;" ::: "memory");
        }

        const uint32_t st  = smb + (uint32_t)(stage * STAGE2);
        const uint32_t sA0 = st + (uint32_t)((wm * 64) * PITCH);
        const uint32_t sA1 = sA0 + (uint32_t)MAT2;
        const uint32_t sBg = st + 2u * MAT2 + (uint32_t)((wn * 32) * PITCH);
        const uint32_t sBu = st + 3u * MAT2 + (uint32_t)((wn * 32) * PITCH);

        #pragma unroll
        for (int ks = 0; ks < 4; ks++) {
            const uint32_t kb = (uint32_t)(ks * 32);
            uint32_t bg[4][2], bu[4][2];
            #pragma unroll
            for (int np = 0; np < 2; np++) {
                uint32_t t4[4];
                ldm_x4(t4, sBg + (uint32_t)(np * 16 * PITCH) + b_off + kb);
                bg[2*np][0] = t4[0]; bg[2*np][1] = t4[1];
                bg[2*np+1][0] = t4[2]; bg[2*np+1][1] = t4[3];
                ldm_x4(t4, sBu + (uint32_t)(np * 16 * PITCH) + b_off + kb);
                bu[2*np][0] = t4[0]; bu[2*np][1] = t4[1];
                bu[2*np+1][0] = t4[2]; bu[2*np+1][1] = t4[3];
            }
            uint32_t af[4][4];
            #pragma unroll
            for (int mi = 0; mi < 4; mi++)
                ldm_x4(af[mi], sA0 + (uint32_t)(mi * 16 * PITCH) + a_off + kb);
            #pragma unroll
            for (int mi = 0; mi < 4; mi++)
                #pragma unroll
                for (int ni = 0; ni < 4; ni++) {
                    mma16816(accg[mi][ni], af[mi], bg[ni]);
                    mma16816(accu[mi][ni], af[mi], bu[ni]);
                }
            #pragma unroll
            for (int mi = 0; mi < 4; mi++)
                ldm_x4(af[mi], sA1 + (uint32_t)(mi * 16 * PITCH) + a_off + kb);
            #pragma unroll
            for (int mi = 0; mi < 4; mi++)
                #pragma unroll
                for (int ni = 0; ni < 4; ni++) {
                    mma16816(accg[mi][ni], af[mi], bg[ni]);
                    mma16816(accu[mi][ni], af[mi], bu[ni]);
                }
        }
        if (++stage == STAGES) stage = 0;
    }

    const int r0b = (int)bm + wm * 64;
    const int c0b = (int)bn + wn * 32;
    #pragma unroll
    for (int mi = 0; mi < 4; mi++) {
        const int r0 = r0b + mi * 16 + (lane >> 2);
        #pragma unroll
        for (int ni = 0; ni < 4; ni++) {
            const int c0 = c0b + ni * 8 + (lane & 3) * 2;
            const float gs0 = __ldg(gs + c0), gs1 = __ldg(gs + c0 + 1);
            const float us0 = __ldg(us + c0), us1 = __ldg(us + c0 + 1);
            float h00 = silu_f(accg[mi][ni][0] * gs0) * (accu[mi][ni][0] * us0);
            float h01 = silu_f(accg[mi][ni][1] * gs1) * (accu[mi][ni][1] * us1);
            float h10 = silu_f(accg[mi][ni][2] * gs0) * (accu[mi][ni][2] * us0);
            float h11 = silu_f(accg[mi][ni][3] * gs1) * (accu[mi][ni][3] * us1);
            __nv_bfloat16 a0, b0, a1, b1, a2, b2, a3, b3;
            split1(h00, a0, b0); split1(h01, a1, b1);
            split1(h10, a2, b2); split1(h11, a3, b3);
            *reinterpret_cast<__nv_bfloat162*>(Hhi + (size_t)r0 * IDIM + c0) =
                __halves2bfloat162(a0, a1);
            *reinterpret_cast<__nv_bfloat162*>(Hlo + (size_t)r0 * IDIM + c0) =
                __halves2bfloat162(b0, b1);
            *reinterpret_cast<__nv_bfloat162*>(Hhi + (size_t)(r0 + 8) * IDIM + c0) =
                __halves2bfloat162(a2, a3);
            *reinterpret_cast<__nv_bfloat162*>(Hlo + (size_t)(r0 + 8) * IDIM + c0) =
                __halves2bfloat162(b2, b3);
        }
    }
}

// ---------------------------------------------------------------------------
// Down GEMM, split-K: blockIdx.z selects K half; partial C per z.
// Cpart[z][m,n] = scale[n]*sum_{k in half z} (Ahi+Alo)[m,k]*B[n,k]
// ---------------------------------------------------------------------------
__global__ __launch_bounds__(THREADS, 1)
void k_gemm_sk(const __nv_bfloat16* __restrict__ Ahi,
               const __nv_bfloat16* __restrict__ Alo,
               const __nv_bfloat16* __restrict__ Bw,
               const float* __restrict__ scale,
               float* __restrict__ Cpart, int N, int Kld, int Kloc) {
    extern __shared__ __align__(128) int8_t sm[];
    const int tid = threadIdx.x, lane = tid & 31, wid = tid >> 5;
    const int wm = wid >> 2, wn = wid & 3;
    const size_t bm = (size_t)blockIdx.x * BM;
    const size_t bn = (size_t)blockIdx.y * BN;
    const int k0g = blockIdx.z * Kloc;

    const __nv_bfloat16* gA0 = Ahi + bm * Kld + k0g;
    const __nv_bfloat16* gA1 = Alo + bm * Kld + k0g;
    const __nv_bfloat16* gB  = Bw  + bn * Kld + k0g;
    float* C = Cpart + (size_t)blockIdx.z * MDIM * HDIM;

    float acc[4][8][4];
    #pragma unroll
    for (int i = 0; i < 4; i++)
        #pragma unroll
        for (int j = 0; j < 8; j++)
            #pragma unroll
            for (int r = 0; r < 4; r++) acc[i][j][r] = 0.0f;

    auto load_stage = [&](int s, int k0) {
        int8_t* base = sm + s * STAGE_B;
        #pragma unroll
        for (int i = 0; i < 4; i++) {
            int c = tid + i * THREADS, row = c >> 3, ch = c & 7;
            cp_async16(base + row * PITCH + ch * 16,
                       gA0 + (size_t)row * Kld + k0 + ch * 8);
        }
        #pragma unroll
        for (int i = 0; i < 4; i++) {
            int c = tid + i * THREADS, row = c >> 3, ch = c & 7;
            cp_async16(base + MAT_A + row * PITCH + ch * 16,
                       gA1 + (size_t)row * Kld + k0 + ch * 8);
        }
        #pragma unroll
        for (int i = 0; i < 8; i++) {
            int c = tid + i * THREADS, row = c >> 3, ch = c & 7;
            cp_async16(base + 2 * MAT_A + row * PITCH + ch * 16,
                       gB + (size_t)row * Kld + k0 + ch * 8);
        }
        asm volatile("cp.async.commit_group;" ::: "memory");
    };

    const int KT = Kloc / BK;
    load_stage(0, 0);
    load_stage(1, BK);

    const uint32_t smb = (uint32_t)__cvta_generic_to_shared(sm);
    const uint32_t a_off = (uint32_t)((lane & 15) * PITCH + (lane >> 4) * 16);
    const uint32_t b_off = (uint32_t)((lane & 7) * PITCH +
                                      ((lane >> 3) & 1) * 16 +
                                      (lane >> 4) * 8 * PITCH);

    int stage = 0;
    for (int kt = 0; kt < KT; kt++) {
        asm volatile("cp.async.wait_group 1;" ::: "memory");
        __syncthreads();
        if (kt + 2 < KT) {
            int s2 = stage + 2; if (s2 >= STAGES) s2 -= STAGES;
            load_stage(s2, (kt + 2) * BK);
        } else {
            asm volatile("cp.async.commit_group;" ::: "memory");
        }

        const uint32_t st  = smb + (uint32_t)(stage * STAGE_B);
        const uint32_t sA0 = st + (uint32_t)((wm * 64) * PITCH);
        const uint32_t sA1 = sA0 + (uint32_t)MAT_A;
        const uint32_t sB  = st + 2u * MAT_A + (uint32_t)((wn * 64) * PITCH);

        #pragma unroll
        for (int ks = 0; ks < 4; ks++) {
            const uint32_t kb = (uint32_t)(ks * 32);
            uint32_t bf[8][2];
            #pragma unroll
            for (int np = 0; np < 4; np++) {
                uint32_t t4[4];
                ldm_x4(t4, sB + (uint32_t)(np * 16 * PITCH) + b_off + kb);
                bf[2 * np][0] = t4[0]; bf[2 * np][1] = t4[1];
                bf[2 * np + 1][0] = t4[2]; bf[2 * np + 1][1] = t4[3];
            }
            uint32_t af[4][4];
            #pragma unroll
            for (int mi = 0; mi < 4; mi++)
                ldm_x4(af[mi], sA0 + (uint32_t)(mi * 16 * PITCH) + a_off + kb);
            #pragma unroll
            for (int mi = 0; mi < 4; mi++)
                #pragma unroll
                for (int ni = 0; ni < 8; ni++)
                    mma16816(acc[mi][ni], af[mi], bf[ni]);
            #pragma unroll
            for (int mi = 0; mi < 4; mi++)
                ldm_x4(af[mi], sA1 + (uint32_t)(mi * 16 * PITCH) + a_off + kb);
            #pragma unroll
            for (int mi = 0; mi < 4; mi++)
                #pragma unroll
                for (int ni = 0; ni < 8; ni++)
                    mma16816(acc[mi][ni], af[mi], bf[ni]);
        }
        if (++stage == STAGES) stage = 0;
    }

    const int r0b = (int)bm + wm * 64;
    const int c0b = (int)bn + wn * 64;
    #pragma unroll
    for (int mi = 0; mi < 4; mi++) {
        const int r0 = r0b + mi * 16 + (lane >> 2);
        #pragma unroll
        for (int ni = 0; ni < 8; ni++) {
            const int c0 = c0b + ni * 8 + (lane & 3) * 2;
            const float s0 = __ldg(scale + c0), s1 = __ldg(scale + c0 + 1);
            float2 v0 = make_float2(acc[mi][ni][0] * s0, acc[mi][ni][1] * s1);
            float2 v1 = make_float2(acc[mi][ni][2] * s0, acc[mi][ni][3] * s1);
            *reinterpret_cast<float2*>(C + (size_t)r0 * N + c0) = v0;
            *reinterpret_cast<float2*>(C + (size_t)(r0 + 8) * N + c0) = v1;
        }
    }
}

// combine the two split-K partials
__global__ void k_add(const float4* __restrict__ p0, const float4* __restrict__ p1,
                      float4* __restrict__ out, int n4) {
    int i = blockIdx.x * blockDim.x + threadIdx.x;
    int stride = gridDim.x * blockDim.x;
    for (; i < n4; i += stride) {
        float4 a = p0[i], b = p1[i];
        out[i] = make_float4(a.x + b.x, a.y + b.y, a.z + b.z, a.w + b.w);
    }
}

// ---------------------------------------------------------------------------
// Elementwise prep kernels
// ---------------------------------------------------------------------------
__global__ void k_convert_w(const int4* __restrict__ wq,
                            __nv_bfloat162* __restrict__ out, int n4) {
    int i = (blockIdx.x * blockDim.x + threadIdx.x) * 2;
    int stride = gridDim.x * blockDim.x * 2;
    for (; i < n4; i += stride) {
        int4 v0 = wq[i], v1 = wq[i + 1];
        out[2 * i + 0] = __halves2bfloat162(__float2bfloat16_rn((float)v0.x),
                                            __float2bfloat16_rn((float)v0.y));
        out[2 * i + 1] = __halves2bfloat162(__float2bfloat16_rn((float)v0.z),
                                            __float2bfloat16_rn((float)v0.w));
        out[2 * i + 2] = __halves2bfloat162(__float2bfloat16_rn((float)v1.x),
                                            __float2bfloat16_rn((float)v1.y));
        out[2 * i + 3] = __halves2bfloat162(__float2bfloat16_rn((float)v1.z),
                                            __float2bfloat16_rn((float)v1.w));
    }
}

__global__ void k_split_x(const float4* __restrict__ x,
                          __nv_bfloat162* __restrict__ hi,
                          __nv_bfloat162* __restrict__ lo, int n4) {
    int i = blockIdx.x * blockDim.x + threadIdx.x;
    int stride = gridDim.x * blockDim.x;
    for (; i < n4; i += stride) {
        float4 v = x[i];
        __nv_bfloat16 h0, l0, h1, l1, h2, l2, h3, l3;
        split1(v.x, h0, l0); split1(v.y, h1, l1);
        split1(v.z, h2, l2); split1(v.w, h3, l3);
        hi[2 * i + 0] = __halves2bfloat162(h0, h1);
        hi[2 * i + 1] = __halves2bfloat162(h2, h3);
        lo[2 * i + 0] = __halves2bfloat162(l0, l1);
        lo[2 * i + 1] = __halves2bfloat162(l2, l3);
    }
}

// ---------------------------------------------------------------------------
// Launch
// ---------------------------------------------------------------------------
extern "C" void kernel_launch(void* const* d_in, const int* in_sizes, int n_in,
                              void* d_out, int out_size) {
    const float* x   = (const float*)d_in[0];
    const int*   gwq = (const int*)  d_in[1];
    const float* gsc = (const float*)d_in[2];
    const int*   uwq = (const int*)  d_in[3];
    const float* usc = (const float*)d_in[4];
    const int*   dwq = (const int*)  d_in[5];
    const float* dsc = (const float*)d_in[6];
    float* out = (float*)d_out;

    cudaFuncSetAttribute(k_gemm_sk, cudaFuncAttributeMaxDynamicSharedMemorySize, SMEM_B);
    cudaFuncSetAttribute(k_gemm_gu, cudaFuncAttributeMaxDynamicSharedMemorySize, SMEM2);

    __nv_bfloat16 *wg, *wu, *wd, *xhi, *xlo, *hhi, *hlo;
    float *part;
    cudaGetSymbolAddress((void**)&wg,  g_wg);
    cudaGetSymbolAddress((void**)&wu,  g_wu);
    cudaGetSymbolAddress((void**)&wd,  g_wd);
    cudaGetSymbolAddress((void**)&xhi, g_xhi);
    cudaGetSymbolAddress((void**)&xlo, g_xlo);
    cudaGetSymbolAddress((void**)&hhi, g_hhi);
    cudaGetSymbolAddress((void**)&hlo, g_hlo);
    cudaGetSymbolAddress((void**)&part, g_part);

    const int CT = 256;
    {
        int n4 = IDIM * HDIM / 4;
        k_convert_w<<<4096, CT>>>((const int4*)gwq, (__nv_bfloat162*)wg, n4);
        k_convert_w<<<4096, CT>>>((const int4*)uwq, (__nv_bfloat162*)wu, n4);
        k_convert_w<<<4096, CT>>>((const int4*)dwq, (__nv_bfloat162*)wd, n4);
    }
    k_split_x<<<4096, CT>>>((const float4*)x, (__nv_bfloat162*)xhi,
                            (__nv_bfloat162*)xlo, MDIM * HDIM / 4);

    dim3 grid1(MDIM / 128, IDIM / 128);   // (32, 112), m fastest for W-slab L2 reuse
    k_gemm_gu<<<grid1, THREADS, SMEM2>>>(xhi, xlo, wg, wu, gsc, usc, hhi, hlo, HDIM);

    dim3 grid2(MDIM / BM, HDIM / BN, 2);  // (32, 16, 2) split-K
    k_gemm_sk<<<grid2, THREADS, SMEM_B>>>(hhi, hlo, wd, dsc, part,
                                          HDIM, IDIM, IDIM / 2);

    k_add<<<2048, CT>>>((const float4*)part,
                        (const float4*)(part + (size_t)MDIM * HDIM),
                        (float4*)out, MDIM * HDIM / 4);
}